// round 12
// baseline (speedup 1.0000x reference)
#include <cuda_runtime.h>
#include <cuda_fp16.h>
#include <math.h>

#define NN 50000
#define EE 800000
#define TT 2
#define NB 49   // scan blocks per type: 49*1024 >= NN

// ---------------- scratch (static device globals; no allocation) ----------------
__device__ __half  g_fh_h[(size_t)TT * NN * 128];  // projected features (fp16, gather path)
__device__ float4  g_el[TT * NN];                  // per-node left attn logits (4 heads)
__device__ float4  g_er[TT * NN];                  // per-node right attn logits
__device__ int     g_deg[TT * NN];
__device__ int     g_start[TT * NN];
__device__ int     g_cnt[TT * NN];
__device__ int     g_col[TT * EE];                 // CSR-by-dst: src ids
__device__ int     g_part[TT * NB];                // per-block degree sums

// ---------------- helpers ----------------
__device__ __forceinline__ float lrelu(float x) { return x > 0.f ? x : 0.2f * x; }

__device__ __forceinline__ float wsum(float v) {
#pragma unroll
    for (int o = 16; o > 0; o >>= 1) v += __shfl_xor_sync(0xffffffffu, v, o);
    return v;
}
__device__ __forceinline__ int wisum(int v) {
#pragma unroll
    for (int o = 16; o > 0; o >>= 1) v += __shfl_xor_sync(0xffffffffu, v, o);
    return v;
}
__device__ __forceinline__ unsigned tf32u(float x) {
    unsigned u; asm("cvt.rna.tf32.f32 %0, %1;" : "=r"(u) : "f"(x)); return u;
}
__device__ __forceinline__ float tf32f(float x) { return __uint_as_float(tf32u(x)); }

// permute k within each 8-group so (k, k+4) become adjacent: [0,4,1,5,2,6,3,7]
__device__ __forceinline__ int kperm(int k) {
    return (k & ~7) | ((k & 3) << 1) | ((k >> 2) & 1);
}

// ---------------- CSR build (per type) ----------------
__global__ void init_kernel(int t) {
    int i = blockIdx.x * blockDim.x + threadIdx.x;
    if (i < NN) { g_deg[t * NN + i] = 0; g_cnt[t * NN + i] = 0; }
}

// plain histogram: return value unused -> ptxas emits fast RED (no-return) form
__global__ void hist_kernel(const int* __restrict__ dst, int t) {
    int i = blockIdx.x * blockDim.x + threadIdx.x;
    if (i < EE) atomicAdd(&g_deg[t * NN + dst[t * EE + i]], 1);
}

__global__ void partial_kernel(int t) {
    __shared__ int red[8];
    int b   = blockIdx.x;
    int tid = threadIdx.x;           // 256
    int lane = tid & 31, wid = tid >> 5;
    int idx = b * 1024 + tid * 4;
    int s = 0;
    if (idx < NN) {
        int4 v = *(const int4*)&g_deg[t * NN + idx];
        s = v.x + v.y + v.z + v.w;
    }
    s = wisum(s);
    if (lane == 0) red[wid] = s;
    __syncthreads();
    if (tid == 0) {
        int tot = 0;
#pragma unroll
        for (int i = 0; i < 8; i++) tot += red[i];
        g_part[t * NB + b] = tot;
    }
}

// local scan + inline prefix over the 49 block partials -> g_start
__global__ void writestart_kernel(int t) {
    __shared__ int wsums[8];
    __shared__ int parts[NB];
    int b   = blockIdx.x;
    int tid = threadIdx.x;           // 256
    int lane = tid & 31, wid = tid >> 5;
    int idx = b * 1024 + tid * 4;

    if (tid < NB) parts[tid] = g_part[t * NB + tid];

    int d0 = 0, d1 = 0, d2 = 0, d3 = 0;
    if (idx < NN) {
        int4 v = *(const int4*)&g_deg[t * NN + idx];
        d0 = v.x; d1 = v.y; d2 = v.z; d3 = v.w;
    }
    int th = d0 + d1 + d2 + d3;
    int incl = th;
#pragma unroll
    for (int off = 1; off < 32; off <<= 1) {
        int u = __shfl_up_sync(0xffffffffu, incl, off);
        if (lane >= off) incl += u;
    }
    int excl = incl - th;
    if (lane == 31) wsums[wid] = incl;
    __syncthreads();
    int woff = 0;
#pragma unroll
    for (int i = 0; i < 8; i++) woff += (i < wid) ? wsums[i] : 0;
    int partoff = 0;
    for (int i = 0; i < b; i++) partoff += parts[i];   // broadcast LDS, <=48 adds
    if (idx < NN) {
        int base = partoff + woff + excl;
        int4 st;
        st.x = base;
        st.y = base + d0;
        st.z = base + d0 + d1;
        st.w = base + d0 + d1 + d2;
        *(int4*)&g_start[t * NN + idx] = st;
    }
}

__global__ void scatter_kernel(const int* __restrict__ src, const int* __restrict__ dst, int t) {
    int i = blockIdx.x * blockDim.x + threadIdx.x;
    if (i >= EE) return;
    int d = dst[t * EE + i];
    int p = g_start[t * NN + d] + atomicAdd(&g_cnt[t * NN + d], 1);
    g_col[t * EE + p] = src[t * EE + i];
}

// ---------------- GEMM (tf32 mma) + fused el/er, fp16 fh output ----------------
// B resident in smem k-major [128][136] (loaded once; conflict-free store+read).
// A chunked [128][36] with k-permutation, register-prefetched next chunk.
// B fragment: b0 = B[k=tig][n], b1 = B[k=tig+4][n] with tig = lane&3.
#define BSTR 136
#define ASTR 36
#define GEMM_SMEM ((128 * BSTR + 128 * ASTR) * 4)
__global__ void __launch_bounds__(256)
gemm_tf32_kernel(const float* __restrict__ feat, const float* __restrict__ W,
                 const float* __restrict__ al, const float* __restrict__ ar, int t) {
    extern __shared__ float smdyn[];
    float* Bs = smdyn;                    // [k=128][n + pad=136]
    float* As = smdyn + 128 * BSTR;       // [row=128][kperm + pad=36]

    const int m0   = blockIdx.x * 128;
    const int tid  = threadIdx.x;
    const int lane = tid & 31;
    const int wr   = (tid >> 5) * 16;
    const int q    = lane >> 2;           // groupID: n-offset / A row
    const int tig  = lane & 3;            // thread-in-group: k-offset
    const int c2   = tig * 2;             // permuted-k offset for A

    const float* Wt = W + t * 16384;

    // load full B once: coalesced float4 LDG, conflict-free STS
#pragma unroll
    for (int i = 0; i < 16; i++) {
        int e4 = (tid + i * 256) * 4;
        int k  = e4 >> 7;
        int n  = e4 & 127;
        float4 v = *(const float4*)(Wt + e4);
        Bs[k * BSTR + n + 0] = tf32f(v.x);
        Bs[k * BSTR + n + 1] = tf32f(v.y);
        Bs[k * BSTR + n + 2] = tf32f(v.z);
        Bs[k * BSTR + n + 3] = tf32f(v.w);
    }

    // load A chunk 0
#pragma unroll
    for (int i = 0; i < 4; i++) {
        int qq  = tid + i * 256;
        int row = qq >> 3;
        int kc  = (qq & 7) * 4;
        int gr  = m0 + row;
        float4 v = (gr < NN) ? *(const float4*)(feat + (size_t)gr * 128 + kc)
                             : make_float4(0.f, 0.f, 0.f, 0.f);
        As[row * ASTR + kperm(kc + 0)] = tf32f(v.x);
        As[row * ASTR + kperm(kc + 1)] = tf32f(v.y);
        As[row * ASTR + kperm(kc + 2)] = tf32f(v.z);
        As[row * ASTR + kperm(kc + 3)] = tf32f(v.w);
    }
    __syncthreads();

    float c[16][4];
#pragma unroll
    for (int j = 0; j < 16; j++)
#pragma unroll
        for (int v = 0; v < 4; v++) c[j][v] = 0.f;

    for (int kt = 0; kt < 128; kt += 32) {
        float4 pf[4];
        const bool more = (kt + 32) < 128;
        if (more) {
#pragma unroll
            for (int i = 0; i < 4; i++) {
                int qq  = tid + i * 256;
                int row = qq >> 3;
                int kc  = (qq & 7) * 4;
                int gr  = m0 + row;
                pf[i] = (gr < NN) ? *(const float4*)(feat + (size_t)gr * 128 + kt + 32 + kc)
                                  : make_float4(0.f, 0.f, 0.f, 0.f);
            }
        }

#pragma unroll
        for (int kk = 0; kk < 32; kk += 8) {
            float2 fa0 = *(const float2*)&As[(wr + q)     * ASTR + kk + c2];
            float2 fa1 = *(const float2*)&As[(wr + q + 8) * ASTR + kk + c2];
            unsigned a0 = __float_as_uint(fa0.x), a2 = __float_as_uint(fa0.y);
            unsigned a1 = __float_as_uint(fa1.x), a3 = __float_as_uint(fa1.y);
            const float* b0row = &Bs[(kt + kk + tig)     * BSTR + q];
            const float* b1row = &Bs[(kt + kk + tig + 4) * BSTR + q];
#pragma unroll
            for (int j = 0; j < 16; j++) {
                unsigned b0 = __float_as_uint(b0row[j * 8]);
                unsigned b1 = __float_as_uint(b1row[j * 8]);
                asm volatile(
                    "mma.sync.aligned.m16n8k8.row.col.f32.tf32.tf32.f32 "
                    "{%0,%1,%2,%3},{%4,%5,%6,%7},{%8,%9},{%0,%1,%2,%3};"
                    : "+f"(c[j][0]), "+f"(c[j][1]), "+f"(c[j][2]), "+f"(c[j][3])
                    : "r"(a0), "r"(a1), "r"(a2), "r"(a3), "r"(b0), "r"(b1));
            }
        }
        __syncthreads();
        if (more) {
#pragma unroll
            for (int i = 0; i < 4; i++) {
                int qq  = tid + i * 256;
                int row = qq >> 3;
                int kc  = (qq & 7) * 4;
                As[row * ASTR + kperm(kc + 0)] = tf32f(pf[i].x);
                As[row * ASTR + kperm(kc + 1)] = tf32f(pf[i].y);
                As[row * ASTR + kperm(kc + 2)] = tf32f(pf[i].z);
                As[row * ASTR + kperm(kc + 3)] = tf32f(pf[i].w);
            }
            __syncthreads();
        }
    }

    // epilogue: lane holds rows r0 = m0+wr+q (c[j][0..1]) and r1 = r0+8 (c[j][2..3]),
    // cols j*8 + 2*tig, +1. head(col) = j>>2.
    int r0 = m0 + wr + q;
    int r1 = r0 + 8;
    __half* fhT = g_fh_h + (size_t)t * NN * 128;

    float el0[4], er0[4], el1[4], er1[4];
#pragma unroll
    for (int h = 0; h < 4; h++) { el0[h] = er0[h] = el1[h] = er1[h] = 0.f; }

#pragma unroll
    for (int j = 0; j < 16; j++) {
        int col = j * 8 + c2;
        int h   = j >> 2;
        float2 a2 = *(const float2*)&al[t * 128 + col];
        float2 b2 = *(const float2*)&ar[t * 128 + col];
        el0[h] += c[j][0] * a2.x + c[j][1] * a2.y;
        er0[h] += c[j][0] * b2.x + c[j][1] * b2.y;
        el1[h] += c[j][2] * a2.x + c[j][3] * a2.y;
        er1[h] += c[j][2] * b2.x + c[j][3] * b2.y;
        if (r0 < NN)
            *(__half2*)(fhT + (size_t)r0 * 128 + col) = __floats2half2_rn(c[j][0], c[j][1]);
        if (r1 < NN)
            *(__half2*)(fhT + (size_t)r1 * 128 + col) = __floats2half2_rn(c[j][2], c[j][3]);
    }
#pragma unroll
    for (int h = 0; h < 4; h++) {
        el0[h] += __shfl_xor_sync(0xffffffffu, el0[h], 1);
        el0[h] += __shfl_xor_sync(0xffffffffu, el0[h], 2);
        er0[h] += __shfl_xor_sync(0xffffffffu, er0[h], 1);
        er0[h] += __shfl_xor_sync(0xffffffffu, er0[h], 2);
        el1[h] += __shfl_xor_sync(0xffffffffu, el1[h], 1);
        el1[h] += __shfl_xor_sync(0xffffffffu, el1[h], 2);
        er1[h] += __shfl_xor_sync(0xffffffffu, er1[h], 1);
        er1[h] += __shfl_xor_sync(0xffffffffu, er1[h], 2);
    }
    if (tig == 0) {
        if (r0 < NN) {
            g_el[t * NN + r0] = make_float4(el0[0], el0[1], el0[2], el0[3]);
            g_er[t * NN + r0] = make_float4(er0[0], er0[1], er0[2], er0[3]);
        }
        if (r1 < NN) {
            g_el[t * NN + r1] = make_float4(el1[0], el1[1], el1[2], el1[3]);
            g_er[t * NN + r1] = make_float4(er1[0], er1[1], er1[2], er1[3]);
        }
    }
}

// ---------------- fused attention + LayerNorm + ELU ----------------
// One WARP per (node, type). Lane l owns output dims 4l..4l+3 (head = l>>3).
__global__ void __launch_bounds__(256)
attn_kernel(const float* __restrict__ bias, const float* __restrict__ lnw,
            const float* __restrict__ lnb, float* __restrict__ out, int t) {
    __shared__ float4 s_w[8][32];
    __shared__ int    s_c[8][32];

    int tid  = threadIdx.x;
    int lane = tid & 31;
    int w    = tid >> 5;
    int n    = blockIdx.x * 8 + w;
    if (n >= NN) return;
    int base = t * NN + n;
    int h    = lane >> 3;

    float4 er4 = g_er[base];
    int beg = g_start[base];
    int deg = g_deg[base];
    const int*    colT = g_col + t * EE;
    const float4* elT  = g_el + t * NN;
    const uint2*  fh2  = (const uint2*)(g_fh_h + (size_t)t * NN * 128);

    float a0 = 0.f, a1 = 0.f, a2 = 0.f, a3 = 0.f;
    float s0 = 0.f, s1 = 0.f, s2 = 0.f, s3 = 0.f;

    for (int pos = 0; pos < deg; pos += 32) {
        int cnt = min(32, deg - pos);
        float4 wv = make_float4(0.f, 0.f, 0.f, 0.f);
        int sc = 0;
        if (lane < cnt) {
            sc = colT[beg + pos + lane];
            float4 el4 = elT[sc];
            wv.x = __expf(lrelu(el4.x + er4.x));
            wv.y = __expf(lrelu(el4.y + er4.y));
            wv.z = __expf(lrelu(el4.z + er4.z));
            wv.w = __expf(lrelu(el4.w + er4.w));
        }
        s0 += wv.x; s1 += wv.y; s2 += wv.z; s3 += wv.w;
        s_c[w][lane] = sc;
        s_w[w][lane] = wv;
        __syncwarp();

        const float* wf = (const float*)&s_w[w][0];
        int e = 0;
        for (; e + 4 <= cnt; e += 4) {
#pragma unroll
            for (int u = 0; u < 4; u++) {
                int   sq = s_c[w][e + u];
                float wt = wf[(e + u) * 4 + h];
                uint2 rv = fh2[(size_t)sq * 32 + lane];
                float2 f0 = __half22float2(*(__half2*)&rv.x);
                float2 f1 = __half22float2(*(__half2*)&rv.y);
                a0 = fmaf(wt, f0.x, a0);
                a1 = fmaf(wt, f0.y, a1);
                a2 = fmaf(wt, f1.x, a2);
                a3 = fmaf(wt, f1.y, a3);
            }
        }
        for (; e < cnt; e++) {
            int   sq = s_c[w][e];
            float wt = wf[e * 4 + h];
            uint2 rv = fh2[(size_t)sq * 32 + lane];
            float2 f0 = __half22float2(*(__half2*)&rv.x);
            float2 f1 = __half22float2(*(__half2*)&rv.y);
            a0 = fmaf(wt, f0.x, a0);
            a1 = fmaf(wt, f0.y, a1);
            a2 = fmaf(wt, f1.x, a2);
            a3 = fmaf(wt, f1.y, a3);
        }
        __syncwarp();
    }

    s0 = wsum(s0); s1 = wsum(s1); s2 = wsum(s2); s3 = wsum(s3);
    float sh  = (h < 2) ? ((h & 1) ? s1 : s0) : ((h & 1) ? s3 : s2);
    float inv = sh > 0.f ? 1.f / sh : 0.f;

    float4 b4 = *(const float4*)&bias[t * 128 + 4 * lane];
    float x0 = a0 * inv + b4.x;
    float x1 = a1 * inv + b4.y;
    float x2 = a2 * inv + b4.z;
    float x3 = a3 * inv + b4.w;

    float mean = wsum(x0 + x1 + x2 + x3) * (1.f / 128.f);
    float d0 = x0 - mean, d1 = x1 - mean, d2 = x2 - mean, d3 = x3 - mean;
    float var = wsum(d0 * d0 + d1 * d1 + d2 * d2 + d3 * d3) * (1.f / 128.f);
    float rinv = rsqrtf(var + 1e-12f);

    float4 w4 = *(const float4*)&lnw[t * 128 + 4 * lane];
    float4 c4 = *(const float4*)&lnb[t * 128 + 4 * lane];
    float y0 = w4.x * (d0 * rinv) + c4.x;
    float y1 = w4.y * (d1 * rinv) + c4.y;
    float y2 = w4.z * (d2 * rinv) + c4.z;
    float y3 = w4.w * (d3 * rinv) + c4.w;
    y0 = y0 > 0.f ? y0 : __expf(y0) - 1.f;
    y1 = y1 > 0.f ? y1 : __expf(y1) - 1.f;
    y2 = y2 > 0.f ? y2 : __expf(y2) - 1.f;
    y3 = y3 > 0.f ? y3 : __expf(y3) - 1.f;

    *(float4*)(out + (size_t)n * (TT * 128) + t * 128 + 4 * lane) =
        make_float4(y0, y1, y2, y3);
}

// ---------------- launch ----------------
extern "C" void kernel_launch(void* const* d_in, const int* in_sizes, int n_in,
                              void* d_out, int out_size) {
    const float* feature = (const float*)d_in[0];
    const int*   src     = (const int*)d_in[1];
    const int*   dst     = (const int*)d_in[2];
    const float* W       = (const float*)d_in[3];
    const float* al      = (const float*)d_in[4];
    const float* ar      = (const float*)d_in[5];
    const float* bias    = (const float*)d_in[6];
    const float* lnw     = (const float*)d_in[7];
    const float* lnb     = (const float*)d_in[8];
    float* out = (float*)d_out;

    static cudaStream_t s2 = nullptr, s3 = nullptr;
    static cudaEvent_t ev_fork = nullptr, ev_csr0 = nullptr, ev_csr1 = nullptr,
                       ev_gemm0 = nullptr, ev_a0 = nullptr;
    if (s2 == nullptr) {
        cudaStreamCreateWithFlags(&s2, cudaStreamNonBlocking);
        cudaStreamCreateWithFlags(&s3, cudaStreamNonBlocking);
        cudaEventCreateWithFlags(&ev_fork, cudaEventDisableTiming);
        cudaEventCreateWithFlags(&ev_csr0, cudaEventDisableTiming);
        cudaEventCreateWithFlags(&ev_csr1, cudaEventDisableTiming);
        cudaEventCreateWithFlags(&ev_gemm0, cudaEventDisableTiming);
        cudaEventCreateWithFlags(&ev_a0, cudaEventDisableTiming);
        cudaFuncSetAttribute(gemm_tf32_kernel,
                             cudaFuncAttributeMaxDynamicSharedMemorySize, GEMM_SMEM);
    }

    const int EB = (EE + 255) / 256;
    const int GB = (NN + 127) / 128;
    const int AB = (NN + 7) / 8;

    // fork
    cudaEventRecord(ev_fork, 0);
    cudaStreamWaitEvent(s2, ev_fork, 0);

    // s2: CSR for t=0, then t=1
    init_kernel<<<(NN + 255) / 256, 256, 0, s2>>>(0);
    hist_kernel<<<EB, 256, 0, s2>>>(dst, 0);
    partial_kernel<<<NB, 256, 0, s2>>>(0);
    writestart_kernel<<<NB, 256, 0, s2>>>(0);
    scatter_kernel<<<EB, 256, 0, s2>>>(src, dst, 0);
    cudaEventRecord(ev_csr0, s2);

    init_kernel<<<(NN + 255) / 256, 256, 0, s2>>>(1);
    hist_kernel<<<EB, 256, 0, s2>>>(dst, 1);
    partial_kernel<<<NB, 256, 0, s2>>>(1);
    writestart_kernel<<<NB, 256, 0, s2>>>(1);
    scatter_kernel<<<EB, 256, 0, s2>>>(src, dst, 1);
    cudaEventRecord(ev_csr1, s2);

    // main: gemm t=0 then t=1
    gemm_tf32_kernel<<<GB, 256, GEMM_SMEM>>>(feature, W, al, ar, 0);
    cudaEventRecord(ev_gemm0, 0);
    gemm_tf32_kernel<<<GB, 256, GEMM_SMEM>>>(feature, W, al, ar, 1);

    // s3: attn t=0 as soon as its inputs are ready (overlaps gemm t=1 / CSR t=1)
    cudaStreamWaitEvent(s3, ev_gemm0, 0);
    cudaStreamWaitEvent(s3, ev_csr0, 0);
    attn_kernel<<<AB, 256, 0, s3>>>(bias, lnw, lnb, out, 0);
    cudaEventRecord(ev_a0, s3);

    // main: attn t=1 after its CSR; then join attn t=0
    cudaStreamWaitEvent(0, ev_csr1, 0);
    attn_kernel<<<AB, 256, 0, 0>>>(bias, lnw, lnb, out, 1);
    cudaStreamWaitEvent(0, ev_a0, 0);
}

// round 13
// speedup vs baseline: 1.1327x; 1.1327x over previous
#include <cuda_runtime.h>
#include <cuda_fp16.h>
#include <math.h>

#define NN 50000
#define EE 800000
#define TT 2
#define NB 49   // scan blocks per type: 49*1024 >= NN

// ---------------- scratch (static device globals; no allocation) ----------------
__device__ __half  g_fh_h[(size_t)TT * NN * 128];  // projected features (fp16, gather path)
__device__ float4  g_el[TT * NN];                  // per-node left attn logits (4 heads)
__device__ float4  g_er[TT * NN];                  // per-node right attn logits
__device__ int     g_deg[TT * NN];
__device__ int     g_start[TT * NN];
__device__ int     g_cnt[TT * NN];
__device__ int     g_col[TT * EE];                 // CSR-by-dst: src ids
__device__ int     g_part[TT * NB];                // per-block degree sums

// ---------------- helpers ----------------
__device__ __forceinline__ float lrelu(float x) { return x > 0.f ? x : 0.2f * x; }

__device__ __forceinline__ float wsum(float v) {
#pragma unroll
    for (int o = 16; o > 0; o >>= 1) v += __shfl_xor_sync(0xffffffffu, v, o);
    return v;
}
__device__ __forceinline__ int wisum(int v) {
#pragma unroll
    for (int o = 16; o > 0; o >>= 1) v += __shfl_xor_sync(0xffffffffu, v, o);
    return v;
}
__device__ __forceinline__ unsigned tf32u(float x) {
    unsigned u; asm("cvt.rna.tf32.f32 %0, %1;" : "=r"(u) : "f"(x)); return u;
}
__device__ __forceinline__ float tf32f(float x) { return __uint_as_float(tf32u(x)); }

// permute k within each 8-group so (k, k+4) become adjacent: [0,4,1,5,2,6,3,7]
__device__ __forceinline__ int kperm(int k) {
    return (k & ~7) | ((k & 3) << 1) | ((k >> 2) & 1);
}

// ---------------- CSR build ----------------
__global__ void init_kernel() {
    int i = blockIdx.x * blockDim.x + threadIdx.x;
    if (i < TT * NN) { g_deg[i] = 0; g_cnt[i] = 0; }
}

// plain histogram, 2 edges/thread; returns unused -> fast RED (no-return) form
__global__ void hist_kernel(const int* __restrict__ dst) {
    int i = (blockIdx.x * blockDim.x + threadIdx.x) * 2;
    int t = blockIdx.y;
    if (i + 1 < EE) {
        int2 d2 = *(const int2*)&dst[t * EE + i];
        atomicAdd(&g_deg[t * NN + d2.x], 1);
        atomicAdd(&g_deg[t * NN + d2.y], 1);
    } else if (i < EE) {
        atomicAdd(&g_deg[t * NN + dst[t * EE + i]], 1);
    }
}

__global__ void partial_kernel() {
    __shared__ int red[8];
    int t   = blockIdx.y;
    int b   = blockIdx.x;
    int tid = threadIdx.x;           // 256
    int lane = tid & 31, wid = tid >> 5;
    int idx = b * 1024 + tid * 4;
    int s = 0;
    if (idx < NN) {
        int4 v = *(const int4*)&g_deg[t * NN + idx];
        s = v.x + v.y + v.z + v.w;
    }
    s = wisum(s);
    if (lane == 0) red[wid] = s;
    __syncthreads();
    if (tid == 0) {
        int tot = 0;
#pragma unroll
        for (int i = 0; i < 8; i++) tot += red[i];
        g_part[t * NB + b] = tot;
    }
}

// local scan + inline prefix over the 49 block partials -> g_start
__global__ void writestart_kernel() {
    __shared__ int wsums[8];
    __shared__ int parts[NB];
    int t   = blockIdx.y;
    int b   = blockIdx.x;
    int tid = threadIdx.x;           // 256
    int lane = tid & 31, wid = tid >> 5;
    int idx = b * 1024 + tid * 4;

    if (tid < NB) parts[tid] = g_part[t * NB + tid];

    int d0 = 0, d1 = 0, d2 = 0, d3 = 0;
    if (idx < NN) {
        int4 v = *(const int4*)&g_deg[t * NN + idx];
        d0 = v.x; d1 = v.y; d2 = v.z; d3 = v.w;
    }
    int th = d0 + d1 + d2 + d3;
    int incl = th;
#pragma unroll
    for (int off = 1; off < 32; off <<= 1) {
        int u = __shfl_up_sync(0xffffffffu, incl, off);
        if (lane >= off) incl += u;
    }
    int excl = incl - th;
    if (lane == 31) wsums[wid] = incl;
    __syncthreads();
    int woff = 0;
#pragma unroll
    for (int i = 0; i < 8; i++) woff += (i < wid) ? wsums[i] : 0;
    int partoff = 0;
    for (int i = 0; i < b; i++) partoff += parts[i];   // broadcast LDS, <=48 adds
    if (idx < NN) {
        int base = partoff + woff + excl;
        int4 st;
        st.x = base;
        st.y = base + d0;
        st.z = base + d0 + d1;
        st.w = base + d0 + d1 + d2;
        *(int4*)&g_start[t * NN + idx] = st;
    }
}

__global__ void scatter_kernel(const int* __restrict__ src, const int* __restrict__ dst) {
    int i = blockIdx.x * blockDim.x + threadIdx.x;
    int t = blockIdx.y;
    if (i >= EE) return;
    int d = dst[t * EE + i];
    int p = g_start[t * NN + d] + atomicAdd(&g_cnt[t * NN + d], 1);
    g_col[t * EE + p] = src[t * EE + i];
}

// ---------------- GEMM (tf32 mma) + fused el/er, fp16 fh output ----------------
// B resident in smem k-major [128][136] (loaded once; conflict-free store+read).
// A chunked [128][36] with k-permutation, register-prefetched next chunk.
// B fragment: b0 = B[k=tig][n], b1 = B[k=tig+4][n] with tig = lane&3.
#define BSTR 136
#define ASTR 36
#define GEMM_SMEM ((128 * BSTR + 128 * ASTR) * 4)
__global__ void __launch_bounds__(256)
gemm_tf32_kernel(const float* __restrict__ feat, const float* __restrict__ W,
                 const float* __restrict__ al, const float* __restrict__ ar) {
    extern __shared__ float smdyn[];
    float* Bs = smdyn;                    // [k=128][n + pad=136]
    float* As = smdyn + 128 * BSTR;       // [row=128][kperm + pad=36]

    const int t    = blockIdx.y;
    const int m0   = blockIdx.x * 128;
    const int tid  = threadIdx.x;
    const int lane = tid & 31;
    const int wr   = (tid >> 5) * 16;
    const int q    = lane >> 2;           // groupID: n-offset / A row
    const int tig  = lane & 3;            // thread-in-group: k-offset
    const int c2   = tig * 2;             // permuted-k offset for A

    const float* Wt = W + t * 16384;

    // load full B once: coalesced float4 LDG, conflict-free STS
#pragma unroll
    for (int i = 0; i < 16; i++) {
        int e4 = (tid + i * 256) * 4;
        int k  = e4 >> 7;
        int n  = e4 & 127;
        float4 v = *(const float4*)(Wt + e4);
        Bs[k * BSTR + n + 0] = tf32f(v.x);
        Bs[k * BSTR + n + 1] = tf32f(v.y);
        Bs[k * BSTR + n + 2] = tf32f(v.z);
        Bs[k * BSTR + n + 3] = tf32f(v.w);
    }

    // load A chunk 0
#pragma unroll
    for (int i = 0; i < 4; i++) {
        int qq  = tid + i * 256;
        int row = qq >> 3;
        int kc  = (qq & 7) * 4;
        int gr  = m0 + row;
        float4 v = (gr < NN) ? *(const float4*)(feat + (size_t)gr * 128 + kc)
                             : make_float4(0.f, 0.f, 0.f, 0.f);
        As[row * ASTR + kperm(kc + 0)] = tf32f(v.x);
        As[row * ASTR + kperm(kc + 1)] = tf32f(v.y);
        As[row * ASTR + kperm(kc + 2)] = tf32f(v.z);
        As[row * ASTR + kperm(kc + 3)] = tf32f(v.w);
    }
    __syncthreads();

    float c[16][4];
#pragma unroll
    for (int j = 0; j < 16; j++)
#pragma unroll
        for (int v = 0; v < 4; v++) c[j][v] = 0.f;

    for (int kt = 0; kt < 128; kt += 32) {
        float4 pf[4];
        const bool more = (kt + 32) < 128;
        if (more) {
#pragma unroll
            for (int i = 0; i < 4; i++) {
                int qq  = tid + i * 256;
                int row = qq >> 3;
                int kc  = (qq & 7) * 4;
                int gr  = m0 + row;
                pf[i] = (gr < NN) ? *(const float4*)(feat + (size_t)gr * 128 + kt + 32 + kc)
                                  : make_float4(0.f, 0.f, 0.f, 0.f);
            }
        }

#pragma unroll
        for (int kk = 0; kk < 32; kk += 8) {
            float2 fa0 = *(const float2*)&As[(wr + q)     * ASTR + kk + c2];
            float2 fa1 = *(const float2*)&As[(wr + q + 8) * ASTR + kk + c2];
            unsigned a0 = __float_as_uint(fa0.x), a2 = __float_as_uint(fa0.y);
            unsigned a1 = __float_as_uint(fa1.x), a3 = __float_as_uint(fa1.y);
            const float* b0row = &Bs[(kt + kk + tig)     * BSTR + q];
            const float* b1row = &Bs[(kt + kk + tig + 4) * BSTR + q];
#pragma unroll
            for (int j = 0; j < 16; j++) {
                unsigned b0 = __float_as_uint(b0row[j * 8]);
                unsigned b1 = __float_as_uint(b1row[j * 8]);
                asm volatile(
                    "mma.sync.aligned.m16n8k8.row.col.f32.tf32.tf32.f32 "
                    "{%0,%1,%2,%3},{%4,%5,%6,%7},{%8,%9},{%0,%1,%2,%3};"
                    : "+f"(c[j][0]), "+f"(c[j][1]), "+f"(c[j][2]), "+f"(c[j][3])
                    : "r"(a0), "r"(a1), "r"(a2), "r"(a3), "r"(b0), "r"(b1));
            }
        }
        __syncthreads();
        if (more) {
#pragma unroll
            for (int i = 0; i < 4; i++) {
                int qq  = tid + i * 256;
                int row = qq >> 3;
                int kc  = (qq & 7) * 4;
                As[row * ASTR + kperm(kc + 0)] = tf32f(pf[i].x);
                As[row * ASTR + kperm(kc + 1)] = tf32f(pf[i].y);
                As[row * ASTR + kperm(kc + 2)] = tf32f(pf[i].z);
                As[row * ASTR + kperm(kc + 3)] = tf32f(pf[i].w);
            }
            __syncthreads();
        }
    }

    // epilogue: lane holds rows r0 = m0+wr+q (c[j][0..1]) and r1 = r0+8 (c[j][2..3]),
    // cols j*8 + 2*tig, +1. head(col) = j>>2.
    int r0 = m0 + wr + q;
    int r1 = r0 + 8;
    __half* fhT = g_fh_h + (size_t)t * NN * 128;

    float el0[4], er0[4], el1[4], er1[4];
#pragma unroll
    for (int h = 0; h < 4; h++) { el0[h] = er0[h] = el1[h] = er1[h] = 0.f; }

#pragma unroll
    for (int j = 0; j < 16; j++) {
        int col = j * 8 + c2;
        int h   = j >> 2;
        float2 a2 = *(const float2*)&al[t * 128 + col];
        float2 b2 = *(const float2*)&ar[t * 128 + col];
        el0[h] += c[j][0] * a2.x + c[j][1] * a2.y;
        er0[h] += c[j][0] * b2.x + c[j][1] * b2.y;
        el1[h] += c[j][2] * a2.x + c[j][3] * a2.y;
        er1[h] += c[j][2] * b2.x + c[j][3] * b2.y;
        if (r0 < NN)
            *(__half2*)(fhT + (size_t)r0 * 128 + col) = __floats2half2_rn(c[j][0], c[j][1]);
        if (r1 < NN)
            *(__half2*)(fhT + (size_t)r1 * 128 + col) = __floats2half2_rn(c[j][2], c[j][3]);
    }
#pragma unroll
    for (int h = 0; h < 4; h++) {
        el0[h] += __shfl_xor_sync(0xffffffffu, el0[h], 1);
        el0[h] += __shfl_xor_sync(0xffffffffu, el0[h], 2);
        er0[h] += __shfl_xor_sync(0xffffffffu, er0[h], 1);
        er0[h] += __shfl_xor_sync(0xffffffffu, er0[h], 2);
        el1[h] += __shfl_xor_sync(0xffffffffu, el1[h], 1);
        el1[h] += __shfl_xor_sync(0xffffffffu, el1[h], 2);
        er1[h] += __shfl_xor_sync(0xffffffffu, er1[h], 1);
        er1[h] += __shfl_xor_sync(0xffffffffu, er1[h], 2);
    }
    if (tig == 0) {
        if (r0 < NN) {
            g_el[t * NN + r0] = make_float4(el0[0], el0[1], el0[2], el0[3]);
            g_er[t * NN + r0] = make_float4(er0[0], er0[1], er0[2], er0[3]);
        }
        if (r1 < NN) {
            g_el[t * NN + r1] = make_float4(el1[0], el1[1], el1[2], el1[3]);
            g_er[t * NN + r1] = make_float4(er1[0], er1[1], er1[2], er1[3]);
        }
    }
}

// ---------------- fused attention + LayerNorm + ELU ----------------
// One WARP per (node, type). Lane l owns output dims 4l..4l+3 (head = l>>3).
__global__ void __launch_bounds__(256)
attn_kernel(const float* __restrict__ bias, const float* __restrict__ lnw,
            const float* __restrict__ lnb, float* __restrict__ out) {
    __shared__ float4 s_w[8][32];
    __shared__ int    s_c[8][32];

    int tid  = threadIdx.x;
    int lane = tid & 31;
    int w    = tid >> 5;
    int n    = blockIdx.x * 8 + w;
    int t    = blockIdx.y;
    if (n >= NN) return;
    int base = t * NN + n;
    int h    = lane >> 3;

    float4 er4 = g_er[base];
    int beg = g_start[base];
    int deg = g_deg[base];
    const int*    colT = g_col + t * EE;
    const float4* elT  = g_el + t * NN;
    const uint2*  fh2  = (const uint2*)(g_fh_h + (size_t)t * NN * 128);

    float a0 = 0.f, a1 = 0.f, a2 = 0.f, a3 = 0.f;
    float s0 = 0.f, s1 = 0.f, s2 = 0.f, s3 = 0.f;

    for (int pos = 0; pos < deg; pos += 32) {
        int cnt = min(32, deg - pos);
        float4 wv = make_float4(0.f, 0.f, 0.f, 0.f);
        int sc = 0;
        if (lane < cnt) {
            sc = colT[beg + pos + lane];
            float4 el4 = elT[sc];
            wv.x = __expf(lrelu(el4.x + er4.x));
            wv.y = __expf(lrelu(el4.y + er4.y));
            wv.z = __expf(lrelu(el4.z + er4.z));
            wv.w = __expf(lrelu(el4.w + er4.w));
        }
        s0 += wv.x; s1 += wv.y; s2 += wv.z; s3 += wv.w;
        s_c[w][lane] = sc;
        s_w[w][lane] = wv;
        __syncwarp();

        const float* wf = (const float*)&s_w[w][0];
        int e = 0;
        for (; e + 4 <= cnt; e += 4) {
#pragma unroll
            for (int u = 0; u < 4; u++) {
                int   sq = s_c[w][e + u];
                float wt = wf[(e + u) * 4 + h];
                uint2 rv = fh2[(size_t)sq * 32 + lane];
                float2 f0 = __half22float2(*(__half2*)&rv.x);
                float2 f1 = __half22float2(*(__half2*)&rv.y);
                a0 = fmaf(wt, f0.x, a0);
                a1 = fmaf(wt, f0.y, a1);
                a2 = fmaf(wt, f1.x, a2);
                a3 = fmaf(wt, f1.y, a3);
            }
        }
        for (; e < cnt; e++) {
            int   sq = s_c[w][e];
            float wt = wf[e * 4 + h];
            uint2 rv = fh2[(size_t)sq * 32 + lane];
            float2 f0 = __half22float2(*(__half2*)&rv.x);
            float2 f1 = __half22float2(*(__half2*)&rv.y);
            a0 = fmaf(wt, f0.x, a0);
            a1 = fmaf(wt, f0.y, a1);
            a2 = fmaf(wt, f1.x, a2);
            a3 = fmaf(wt, f1.y, a3);
        }
        __syncwarp();
    }

    s0 = wsum(s0); s1 = wsum(s1); s2 = wsum(s2); s3 = wsum(s3);
    float sh  = (h < 2) ? ((h & 1) ? s1 : s0) : ((h & 1) ? s3 : s2);
    float inv = sh > 0.f ? 1.f / sh : 0.f;

    float4 b4 = *(const float4*)&bias[t * 128 + 4 * lane];
    float x0 = a0 * inv + b4.x;
    float x1 = a1 * inv + b4.y;
    float x2 = a2 * inv + b4.z;
    float x3 = a3 * inv + b4.w;

    float mean = wsum(x0 + x1 + x2 + x3) * (1.f / 128.f);
    float d0 = x0 - mean, d1 = x1 - mean, d2 = x2 - mean, d3 = x3 - mean;
    float var = wsum(d0 * d0 + d1 * d1 + d2 * d2 + d3 * d3) * (1.f / 128.f);
    float rinv = rsqrtf(var + 1e-12f);

    float4 w4 = *(const float4*)&lnw[t * 128 + 4 * lane];
    float4 c4 = *(const float4*)&lnb[t * 128 + 4 * lane];
    float y0 = w4.x * (d0 * rinv) + c4.x;
    float y1 = w4.y * (d1 * rinv) + c4.y;
    float y2 = w4.z * (d2 * rinv) + c4.z;
    float y3 = w4.w * (d3 * rinv) + c4.w;
    y0 = y0 > 0.f ? y0 : __expf(y0) - 1.f;
    y1 = y1 > 0.f ? y1 : __expf(y1) - 1.f;
    y2 = y2 > 0.f ? y2 : __expf(y2) - 1.f;
    y3 = y3 > 0.f ? y3 : __expf(y3) - 1.f;

    *(float4*)(out + (size_t)n * (TT * 128) + t * 128 + 4 * lane) =
        make_float4(y0, y1, y2, y3);
}

// ---------------- launch ----------------
extern "C" void kernel_launch(void* const* d_in, const int* in_sizes, int n_in,
                              void* d_out, int out_size) {
    const float* feature = (const float*)d_in[0];
    const int*   src     = (const int*)d_in[1];
    const int*   dst     = (const int*)d_in[2];
    const float* W       = (const float*)d_in[3];
    const float* al      = (const float*)d_in[4];
    const float* ar      = (const float*)d_in[5];
    const float* bias    = (const float*)d_in[6];
    const float* lnw     = (const float*)d_in[7];
    const float* lnb     = (const float*)d_in[8];
    float* out = (float*)d_out;

    static cudaStream_t s2 = nullptr;
    static cudaEvent_t ev_fork = nullptr, ev_join = nullptr;
    if (s2 == nullptr) {
        cudaStreamCreateWithFlags(&s2, cudaStreamNonBlocking);
        cudaEventCreateWithFlags(&ev_fork, cudaEventDisableTiming);
        cudaEventCreateWithFlags(&ev_join, cudaEventDisableTiming);
        cudaFuncSetAttribute(gemm_tf32_kernel,
                             cudaFuncAttributeMaxDynamicSharedMemorySize, GEMM_SMEM);
    }

    // fork: CSR build on s2, GEMM on the main (capture) stream
    cudaEventRecord(ev_fork, 0);
    cudaStreamWaitEvent(s2, ev_fork, 0);

    init_kernel<<<(TT * NN + 255) / 256, 256, 0, s2>>>();
    hist_kernel<<<dim3((EE / 2 + 255) / 256, TT), 256, 0, s2>>>(dst);
    partial_kernel<<<dim3(NB, TT), 256, 0, s2>>>();
    writestart_kernel<<<dim3(NB, TT), 256, 0, s2>>>();
    scatter_kernel<<<dim3((EE + 255) / 256, TT), 256, 0, s2>>>(src, dst);

    gemm_tf32_kernel<<<dim3((NN + 127) / 128, TT), 256, GEMM_SMEM>>>(feature, W, al, ar);

    // join, then fused attention
    cudaEventRecord(ev_join, s2);
    cudaStreamWaitEvent(0, ev_join, 0);
    attn_kernel<<<dim3((NN + 7) / 8, TT), 256>>>(bias, lnw, lnb, out);
}